// round 1
// baseline (speedup 1.0000x reference)
#include <cuda_runtime.h>

#define BB 16
#define SS 1024
#define DD 1024
#define NH 16
#define HD 64
#define M_TOT (BB*SS)

// Scratch (allocation-free requirement): 4 x 64MB
__device__ float g_q[(size_t)BB*NH*SS*HD];
__device__ float g_k[(size_t)BB*NH*SS*HD];
__device__ float g_v[(size_t)BB*NH*SS*HD];
__device__ float g_ao[(size_t)M_TOT*DD];

// ---------------------------------------------------------------------------
// Fused QKV GEMM + bias + RoPE.  C[m,n] = sum_k x[m,k]*W[n,k] + b[n]
// grid: (N/128=8, M/128=128, 3)  z selects Q/K/V.  Q,K get RoPE.
// Output layout: ((b*NH+h)*S + s)*HD + hd
// ---------------------------------------------------------------------------
__global__ void __launch_bounds__(256) qkv_kernel(
    const float* __restrict__ x,
    const float* __restrict__ Wq, const float* __restrict__ bq,
    const float* __restrict__ Wk, const float* __restrict__ bk,
    const float* __restrict__ Wv, const float* __restrict__ bv,
    const float* __restrict__ cosp, const float* __restrict__ sinp)
{
    __shared__ __align__(16) float As[8][132];
    __shared__ __align__(16) float Bs[8][132];

    const int z = blockIdx.z;
    const float* W    = (z == 0) ? Wq : (z == 1) ? Wk : Wv;
    const float* bias = (z == 0) ? bq : (z == 1) ? bk : bv;
    float* outp       = (z == 0) ? g_q : (z == 1) ? g_k : g_v;
    const bool rope   = (z < 2);

    const int tid  = threadIdx.x;
    const int brow = blockIdx.y;
    const int bcol = blockIdx.x;

    const float* Ab = x + (size_t)brow * 128 * DD;
    const float* Wb = W + (size_t)bcol * 128 * DD;

    const int lr = tid >> 1;          // 0..127
    const int lc = (tid & 1) * 4;     // 0 or 4
    const int tx = tid & 15, ty = tid >> 4;

    float acc[8][8];
    #pragma unroll
    for (int i = 0; i < 8; i++)
        #pragma unroll
        for (int j = 0; j < 8; j++) acc[i][j] = 0.f;

    for (int k0 = 0; k0 < DD; k0 += 8) {
        float4 a = *(const float4*)(Ab + (size_t)lr * DD + k0 + lc);
        float4 w = *(const float4*)(Wb + (size_t)lr * DD + k0 + lc);
        As[lc+0][lr] = a.x; As[lc+1][lr] = a.y; As[lc+2][lr] = a.z; As[lc+3][lr] = a.w;
        Bs[lc+0][lr] = w.x; Bs[lc+1][lr] = w.y; Bs[lc+2][lr] = w.z; Bs[lc+3][lr] = w.w;
        __syncthreads();
        #pragma unroll
        for (int k = 0; k < 8; k++) {
            float4 a0 = *(const float4*)&As[k][ty*4];
            float4 a1 = *(const float4*)&As[k][ty*4 + 64];
            float4 b0 = *(const float4*)&Bs[k][tx*4];
            float4 b1 = *(const float4*)&Bs[k][tx*4 + 64];
            float ar[8] = {a0.x,a0.y,a0.z,a0.w,a1.x,a1.y,a1.z,a1.w};
            float br[8] = {b0.x,b0.y,b0.z,b0.w,b1.x,b1.y,b1.z,b1.w};
            #pragma unroll
            for (int i = 0; i < 8; i++)
                #pragma unroll
                for (int j = 0; j < 8; j++)
                    acc[i][j] += ar[i] * br[j];
        }
        __syncthreads();
    }

    // Epilogue: bias + (optional) RoPE, write to (b,h,s,hd) layout
    #pragma unroll
    for (int ii = 0; ii < 2; ii++) {
        #pragma unroll
        for (int i = 0; i < 4; i++) {
            int row = ty*4 + i + ii*64;
            int m = brow*128 + row;
            int b = m >> 10, s = m & 1023;
            #pragma unroll
            for (int jj = 0; jj < 2; jj++) {
                int col0 = tx*4 + jj*64;
                int n0 = bcol*128 + col0;
                int h = n0 >> 6, hd0 = n0 & 63;
                float v0 = acc[ii*4+i][jj*4+0] + bias[n0+0];
                float v1 = acc[ii*4+i][jj*4+1] + bias[n0+1];
                float v2 = acc[ii*4+i][jj*4+2] + bias[n0+2];
                float v3 = acc[ii*4+i][jj*4+3] + bias[n0+3];
                if (rope) {
                    const float* cs = cosp + s*HD + hd0;
                    const float* sn = sinp + s*HD + hd0;
                    float o0 = v0*cs[0] - v1*sn[0];
                    float o1 = v1*cs[1] + v0*sn[1];
                    float o2 = v2*cs[2] - v3*sn[2];
                    float o3 = v3*cs[3] + v2*sn[3];
                    v0 = o0; v1 = o1; v2 = o2; v3 = o3;
                }
                float4 val = make_float4(v0, v1, v2, v3);
                *(float4*)(outp + ((size_t)(b*NH + h)*SS + s)*HD + hd0) = val;
            }
        }
    }
}

// ---------------------------------------------------------------------------
// Flash attention. grid (S/64, NH, B), 256 threads, dynamic smem 51KB.
// Q tile 64x64 (transposed, pre-scaled), K chunk transposed (buffer reused
// for P after scores), V chunk direct.  Online softmax.
// Output written in (b, s, h*HD+hd) layout -> plain GEMM input.
// ---------------------------------------------------------------------------
__global__ void __launch_bounds__(256) attn_kernel()
{
    extern __shared__ float sm[];
    float* SQ = sm;               // [hd][r]  64x68
    float* SK = sm + 64*68;       // [hd][c] then P [r][c]
    float* SV = sm + 2*64*68;     // [j][c]

    const int tid = threadIdx.x;
    const int q0 = blockIdx.x * 64;
    const int h = blockIdx.y, b = blockIdx.z;
    const int bh = b*NH + h;
    const float* Qg  = g_q + ((size_t)bh*SS + q0) * HD;
    const float* Kg0 = g_k + (size_t)bh*SS*HD;
    const float* Vg0 = g_v + (size_t)bh*SS*HD;

    // load Q transposed, pre-scaled by HD^-0.5 = 1/8
    {
        int r = tid & 63, grp = tid >> 6, hdb = grp*16;
        #pragma unroll
        for (int i = 0; i < 4; i++) {
            float4 v = *(const float4*)(Qg + r*HD + hdb + i*4);
            SQ[(hdb+i*4+0)*68 + r] = v.x * 0.125f;
            SQ[(hdb+i*4+1)*68 + r] = v.y * 0.125f;
            SQ[(hdb+i*4+2)*68 + r] = v.z * 0.125f;
            SQ[(hdb+i*4+3)*68 + r] = v.w * 0.125f;
        }
    }

    const int tx = tid & 15, ty = tid >> 4;
    const int r = tid >> 2, sub = tid & 3, cb = sub*16;

    float o[16];
    #pragma unroll
    for (int i = 0; i < 16; i++) o[i] = 0.f;
    float m_run = -1e30f, l_run = 0.f;

    for (int kv0 = 0; kv0 < SS; kv0 += 64) {
        __syncthreads();   // prev PV done before overwriting K/V
        {
            int rr = tid & 63, grp = tid >> 6, hdb = grp*16;
            const float* Kg = Kg0 + (size_t)(kv0 + rr)*HD;
            #pragma unroll
            for (int i = 0; i < 4; i++) {
                float4 v = *(const float4*)(Kg + hdb + i*4);
                SK[(hdb+i*4+0)*68 + rr] = v.x;
                SK[(hdb+i*4+1)*68 + rr] = v.y;
                SK[(hdb+i*4+2)*68 + rr] = v.z;
                SK[(hdb+i*4+3)*68 + rr] = v.w;
            }
            int j = tid >> 2, cb2 = (tid & 3)*16;
            const float* Vg = Vg0 + (size_t)(kv0 + j)*HD + cb2;
            #pragma unroll
            for (int i = 0; i < 4; i++)
                *(float4*)(SV + j*68 + cb2 + i*4) = *(const float4*)(Vg + i*4);
        }
        __syncthreads();

        // scores: 4x4 register tile over 64x64
        float acc[4][4];
        #pragma unroll
        for (int i = 0; i < 4; i++)
            #pragma unroll
            for (int j = 0; j < 4; j++) acc[i][j] = 0.f;
        #pragma unroll 8
        for (int k = 0; k < 64; k++) {
            float4 qv = *(const float4*)(SQ + k*68 + ty*4);
            float4 kv = *(const float4*)(SK + k*68 + tx*4);
            float qa[4] = {qv.x, qv.y, qv.z, qv.w};
            float ka[4] = {kv.x, kv.y, kv.z, kv.w};
            #pragma unroll
            for (int i = 0; i < 4; i++)
                #pragma unroll
                for (int j = 0; j < 4; j++)
                    acc[i][j] += qa[i] * ka[j];
        }
        __syncthreads();   // everyone done reading SK -> reuse as P
        #pragma unroll
        for (int i = 0; i < 4; i++) {
            float4 pv = make_float4(acc[i][0], acc[i][1], acc[i][2], acc[i][3]);
            *(float4*)(SK + (ty*4+i)*68 + tx*4) = pv;
        }
        __syncthreads();

        // online softmax on this thread's 16 cols of row r
        float p[16];
        #pragma unroll
        for (int i = 0; i < 4; i++) {
            float4 pv = *(const float4*)(SK + r*68 + cb + i*4);
            p[i*4+0] = pv.x; p[i*4+1] = pv.y; p[i*4+2] = pv.z; p[i*4+3] = pv.w;
        }
        float mloc = p[0];
        #pragma unroll
        for (int i = 1; i < 16; i++) mloc = fmaxf(mloc, p[i]);
        mloc = fmaxf(mloc, __shfl_xor_sync(0xffffffffu, mloc, 1));
        mloc = fmaxf(mloc, __shfl_xor_sync(0xffffffffu, mloc, 2));
        float m_new = fmaxf(m_run, mloc);
        float alpha = __expf(m_run - m_new);
        float sloc = 0.f;
        #pragma unroll
        for (int i = 0; i < 16; i++) { p[i] = __expf(p[i] - m_new); sloc += p[i]; }
        #pragma unroll
        for (int i = 0; i < 4; i++) {
            float4 pv = make_float4(p[i*4+0], p[i*4+1], p[i*4+2], p[i*4+3]);
            *(float4*)(SK + r*68 + cb + i*4) = pv;
        }
        l_run = l_run * alpha + sloc;
        m_run = m_new;
        #pragma unroll
        for (int i = 0; i < 16; i++) o[i] *= alpha;
        __syncwarp();      // P row written by same-warp lanes

        // PV accumulate
        #pragma unroll 4
        for (int j = 0; j < 64; j++) {
            float pj = SK[r*68 + j];
            float4 vA = *(const float4*)(SV + j*68 + cb);
            float4 vB = *(const float4*)(SV + j*68 + cb + 4);
            float4 vC = *(const float4*)(SV + j*68 + cb + 8);
            float4 vD = *(const float4*)(SV + j*68 + cb + 12);
            o[0]  += pj*vA.x; o[1]  += pj*vA.y; o[2]  += pj*vA.z; o[3]  += pj*vA.w;
            o[4]  += pj*vB.x; o[5]  += pj*vB.y; o[6]  += pj*vB.z; o[7]  += pj*vB.w;
            o[8]  += pj*vC.x; o[9]  += pj*vC.y; o[10] += pj*vC.z; o[11] += pj*vC.w;
            o[12] += pj*vD.x; o[13] += pj*vD.y; o[14] += pj*vD.z; o[15] += pj*vD.w;
        }
    }

    float l = l_run;
    l += __shfl_xor_sync(0xffffffffu, l, 1);
    l += __shfl_xor_sync(0xffffffffu, l, 2);
    float inv = 1.0f / l;
    float* Og = g_ao + ((size_t)(b*SS + q0 + r))*DD + h*HD + cb;
    *(float4*)(Og + 0)  = make_float4(o[0]*inv,  o[1]*inv,  o[2]*inv,  o[3]*inv);
    *(float4*)(Og + 4)  = make_float4(o[4]*inv,  o[5]*inv,  o[6]*inv,  o[7]*inv);
    *(float4*)(Og + 8)  = make_float4(o[8]*inv,  o[9]*inv,  o[10]*inv, o[11]*inv);
    *(float4*)(Og + 12) = make_float4(o[12]*inv, o[13]*inv, o[14]*inv, o[15]*inv);
}

// ---------------------------------------------------------------------------
// Output projection: d_out[m,n] = sum_k g_ao[m,k]*Wo[n,k] + bo[n]
// ---------------------------------------------------------------------------
__global__ void __launch_bounds__(256) oproj_kernel(
    const float* __restrict__ Wo, const float* __restrict__ bo,
    float* __restrict__ out)
{
    __shared__ __align__(16) float As[8][132];
    __shared__ __align__(16) float Bs[8][132];

    const int tid  = threadIdx.x;
    const int brow = blockIdx.y;
    const int bcol = blockIdx.x;

    const float* Ab = g_ao + (size_t)brow * 128 * DD;
    const float* Wb = Wo   + (size_t)bcol * 128 * DD;

    const int lr = tid >> 1;
    const int lc = (tid & 1) * 4;
    const int tx = tid & 15, ty = tid >> 4;

    float acc[8][8];
    #pragma unroll
    for (int i = 0; i < 8; i++)
        #pragma unroll
        for (int j = 0; j < 8; j++) acc[i][j] = 0.f;

    for (int k0 = 0; k0 < DD; k0 += 8) {
        float4 a = *(const float4*)(Ab + (size_t)lr * DD + k0 + lc);
        float4 w = *(const float4*)(Wb + (size_t)lr * DD + k0 + lc);
        As[lc+0][lr] = a.x; As[lc+1][lr] = a.y; As[lc+2][lr] = a.z; As[lc+3][lr] = a.w;
        Bs[lc+0][lr] = w.x; Bs[lc+1][lr] = w.y; Bs[lc+2][lr] = w.z; Bs[lc+3][lr] = w.w;
        __syncthreads();
        #pragma unroll
        for (int k = 0; k < 8; k++) {
            float4 a0 = *(const float4*)&As[k][ty*4];
            float4 a1 = *(const float4*)&As[k][ty*4 + 64];
            float4 b0 = *(const float4*)&Bs[k][tx*4];
            float4 b1 = *(const float4*)&Bs[k][tx*4 + 64];
            float ar[8] = {a0.x,a0.y,a0.z,a0.w,a1.x,a1.y,a1.z,a1.w};
            float br[8] = {b0.x,b0.y,b0.z,b0.w,b1.x,b1.y,b1.z,b1.w};
            #pragma unroll
            for (int i = 0; i < 8; i++)
                #pragma unroll
                for (int j = 0; j < 8; j++)
                    acc[i][j] += ar[i] * br[j];
        }
        __syncthreads();
    }

    #pragma unroll
    for (int ii = 0; ii < 2; ii++) {
        #pragma unroll
        for (int i = 0; i < 4; i++) {
            int m = brow*128 + ty*4 + i + ii*64;
            #pragma unroll
            for (int jj = 0; jj < 2; jj++) {
                int n0 = bcol*128 + tx*4 + jj*64;
                float4 v = make_float4(acc[ii*4+i][jj*4+0] + bo[n0+0],
                                       acc[ii*4+i][jj*4+1] + bo[n0+1],
                                       acc[ii*4+i][jj*4+2] + bo[n0+2],
                                       acc[ii*4+i][jj*4+3] + bo[n0+3]);
                *(float4*)(out + (size_t)m*DD + n0) = v;
            }
        }
    }
}

extern "C" void kernel_launch(void* const* d_in, const int* in_sizes, int n_in,
                              void* d_out, int out_size)
{
    const float* x    = (const float*)d_in[0];
    const float* cosp = (const float*)d_in[1];
    const float* sinp = (const float*)d_in[2];
    const float* Wq   = (const float*)d_in[3];
    const float* bq   = (const float*)d_in[4];
    const float* Wk   = (const float*)d_in[5];
    const float* bk   = (const float*)d_in[6];
    const float* Wv   = (const float*)d_in[7];
    const float* bv   = (const float*)d_in[8];
    const float* Wo   = (const float*)d_in[9];
    const float* bo   = (const float*)d_in[10];
    float* out = (float*)d_out;

    (void)in_sizes; (void)n_in; (void)out_size;

    const int attn_smem = 3 * 64 * 68 * 4;  // 52224 B
    cudaFuncSetAttribute((const void*)attn_kernel,
                         cudaFuncAttributeMaxDynamicSharedMemorySize, attn_smem);

    qkv_kernel<<<dim3(8, 128, 3), 256>>>(x, Wq, bq, Wk, bk, Wv, bv, cosp, sinp);
    attn_kernel<<<dim3(SS/64, NH, BB), 256, attn_smem>>>();
    oproj_kernel<<<dim3(8, 128), 256>>>(Wo, bo, out);
}

// round 2
// speedup vs baseline: 2.9532x; 2.9532x over previous
#include <cuda_runtime.h>
#include <cstdint>

#define BB 16
#define SS 1024
#define DD 1024
#define NH 16
#define HD 64

// Scratch (allocation-free requirement)
__device__ float g_q[(size_t)BB*NH*SS*HD];
__device__ float g_k[(size_t)BB*NH*SS*HD];
__device__ float g_v[(size_t)BB*NH*SS*HD];
__device__ float g_ao[(size_t)BB*SS*DD];

__device__ __forceinline__ float to_tf32(float x){
    float r; asm("cvt.rna.tf32.f32 %0, %1;" : "=f"(r) : "f"(x)); return r;
}

__device__ __forceinline__ void mma_tf32(float* d,
    float a0, float a1, float a2, float a3, float b0, float b1)
{
    asm volatile("mma.sync.aligned.m16n8k8.row.col.f32.tf32.tf32.f32 "
        "{%0,%1,%2,%3}, {%4,%5,%6,%7}, {%8,%9}, {%0,%1,%2,%3};"
        : "+f"(d[0]), "+f"(d[1]), "+f"(d[2]), "+f"(d[3])
        : "r"(__float_as_uint(a0)), "r"(__float_as_uint(a1)),
          "r"(__float_as_uint(a2)), "r"(__float_as_uint(a3)),
          "r"(__float_as_uint(b0)), "r"(__float_as_uint(b1)));
}

// Store 8 consecutive-k fp32 values into k-pair-permuted tf32 smem layout:
// within an 8-k block, position 2i holds k=i, 2i+1 holds k=i+4.
__device__ __forceinline__ void st_pair(float* s, float4 u, float4 v){
    ((float2*)s)[0] = make_float2(to_tf32(u.x), to_tf32(v.x));
    ((float2*)s)[1] = make_float2(to_tf32(u.y), to_tf32(v.y));
    ((float2*)s)[2] = make_float2(to_tf32(u.z), to_tf32(v.z));
    ((float2*)s)[3] = make_float2(to_tf32(u.w), to_tf32(v.w));
}

// One k-tile (16) of mma work from permuted smem tiles (stride 24 floats).
__device__ __forceinline__ void gemm_step(const float* sA, const float* sB,
                                          int wm, int wn, int lr, int lc,
                                          float (&d)[2][8][4])
{
    #pragma unroll
    for (int ks = 0; ks < 2; ks++){
        const float* sa = sA + (wm + lr)*24 + ks*8 + 2*lc;
        float2 a02_0 = *(const float2*)(sa);
        float2 a13_0 = *(const float2*)(sa + 8*24);
        float2 a02_1 = *(const float2*)(sa + 16*24);
        float2 a13_1 = *(const float2*)(sa + 24*24);
        #pragma unroll
        for (int nt = 0; nt < 8; nt++){
            float2 b = *(const float2*)(sB + (wn + nt*8 + lr)*24 + ks*8 + 2*lc);
            mma_tf32(d[0][nt], a02_0.x, a13_0.x, a02_0.y, a13_0.y, b.x, b.y);
            mma_tf32(d[1][nt], a02_1.x, a13_1.x, a02_1.y, a13_1.y, b.x, b.y);
        }
    }
}

// Shared GEMM mainloop: C(128x128) = A(128xK) @ B(128xK)^T, K=1024, tf32 mma.
__device__ __forceinline__ void gemm_main(const float* __restrict__ Ab,
                                          const float* __restrict__ Bb,
                                          float* sm, float (&d)[2][8][4])
{
    float* bufA[2] = {sm,        sm + 3072};
    float* bufB[2] = {sm + 6144, sm + 9216};

    const int tid  = threadIdx.x;
    const int warp = tid >> 5, lane = tid & 31;
    const int wm = (warp >> 1) * 32, wn = (warp & 1) * 64;
    const int lr = lane >> 2, lc = lane & 3;

    const int ldrow = tid >> 1;
    const int kg    = (tid & 1) * 8;
    const float* aptr = Ab + (size_t)ldrow * DD + kg;
    const float* bptr = Bb + (size_t)ldrow * DD + kg;
    const int soff = ldrow*24 + kg;

    // preload tile 0
    float4 ua = *(const float4*)(aptr);
    float4 va = *(const float4*)(aptr + 4);
    float4 ub = *(const float4*)(bptr);
    float4 vb = *(const float4*)(bptr + 4);
    st_pair(bufA[0] + soff, ua, va);
    st_pair(bufB[0] + soff, ub, vb);
    __syncthreads();

    for (int kt = 0; kt < 64; kt++){
        int cur = kt & 1;
        if (kt < 63){
            const float* ap = aptr + (kt+1)*16;
            const float* bp = bptr + (kt+1)*16;
            ua = *(const float4*)(ap);
            va = *(const float4*)(ap + 4);
            ub = *(const float4*)(bp);
            vb = *(const float4*)(bp + 4);
        }
        gemm_step(bufA[cur], bufB[cur], wm, wn, lr, lc, d);
        if (kt < 63){
            st_pair(bufA[cur^1] + soff, ua, va);
            st_pair(bufB[cur^1] + soff, ub, vb);
            __syncthreads();
        }
    }
}

// ---------------------------------------------------------------------------
// Fused QKV projection + bias + RoPE.  grid (8, 128, 3)
// ---------------------------------------------------------------------------
__global__ void __launch_bounds__(256) qkv_kernel(
    const float* __restrict__ x,
    const float* __restrict__ Wq, const float* __restrict__ bq,
    const float* __restrict__ Wk, const float* __restrict__ bk,
    const float* __restrict__ Wv, const float* __restrict__ bv,
    const float* __restrict__ cosp, const float* __restrict__ sinp)
{
    extern __shared__ float sm[];
    const int z = blockIdx.z;
    const float* W    = (z == 0) ? Wq : (z == 1) ? Wk : Wv;
    const float* bias = (z == 0) ? bq : (z == 1) ? bk : bv;
    float* outp       = (z == 0) ? g_q : (z == 1) ? g_k : g_v;

    float d[2][8][4] = {};
    gemm_main(x + (size_t)blockIdx.y*128*DD, W + (size_t)blockIdx.x*128*DD, sm, d);

    const int tid = threadIdx.x;
    const int warp = tid >> 5, lane = tid & 31;
    const int wm = (warp >> 1) * 32, wn = (warp & 1) * 64;
    const int lr = lane >> 2, lc = lane & 3;

    #pragma unroll
    for (int mt = 0; mt < 2; mt++){
        #pragma unroll
        for (int rh = 0; rh < 2; rh++){
            int m = blockIdx.y*128 + wm + mt*16 + rh*8 + lr;
            int bb = m >> 10, s = m & 1023;
            #pragma unroll
            for (int nt = 0; nt < 8; nt++){
                int n = blockIdx.x*128 + wn + nt*8 + 2*lc;
                float2 bi = *(const float2*)(bias + n);
                float v0 = d[mt][nt][rh*2+0] + bi.x;
                float v1 = d[mt][nt][rh*2+1] + bi.y;
                int hh = n >> 6, hd0 = n & 63;
                if (z < 2){
                    float2 cs = *(const float2*)(cosp + s*HD + hd0);
                    float2 sn = *(const float2*)(sinp + s*HD + hd0);
                    float r0 = v0*cs.x - v1*sn.x;
                    float r1 = v1*cs.y + v0*sn.y;
                    v0 = r0; v1 = r1;
                }
                *(float2*)(outp + ((size_t)(bb*NH + hh)*SS + s)*HD + hd0) =
                    make_float2(v0, v1);
            }
        }
    }
}

// ---------------------------------------------------------------------------
// Flash attention, tf32 mma.  grid (8, NH, BB), 256 thr, dyn smem 72KB.
// Each warp owns 16 q rows fully (softmax in registers + quad shuffles).
// ---------------------------------------------------------------------------
__global__ void __launch_bounds__(256) attn_kernel()
{
    extern __shared__ float sm[];
    float* sK = sm;            // [64][72]
    float* sV = sm + 64*72;    // [64][72]
    float* sP = sm + 2*64*72;  // [128][72]

    const int tid = threadIdx.x;
    const int warp = tid >> 5, lane = tid & 31;
    const int lr = lane >> 2, lc = lane & 3;
    const int wm = warp * 16;
    const int q0 = blockIdx.x * 128;
    const int h = blockIdx.y, b = blockIdx.z;
    const int bh = b*NH + h;
    const float* Qg = g_q + (size_t)bh*SS*HD;
    const float* Kg = g_k + (size_t)bh*SS*HD;
    const float* Vg = g_v + (size_t)bh*SS*HD;

    // Q fragments resident in registers (pre-scaled by HD^-0.5, tf32-rounded)
    float qa[8][4];
    {
        const float* q0p = Qg + (size_t)(q0 + wm + lr)*HD;
        const float* q1p = q0p + 8*HD;
        #pragma unroll
        for (int ks = 0; ks < 8; ks++){
            int c = ks*8 + lc;
            qa[ks][0] = to_tf32(q0p[c]   * 0.125f);
            qa[ks][1] = to_tf32(q1p[c]   * 0.125f);
            qa[ks][2] = to_tf32(q0p[c+4] * 0.125f);
            qa[ks][3] = to_tf32(q1p[c+4] * 0.125f);
        }
    }

    float o[8][4] = {};
    float m0 = -1e30f, m1 = -1e30f, l0 = 0.f, l1 = 0.f;

    const int cprow = tid >> 2;          // 0..63
    const int cpcol = (tid & 3) * 16;

    for (int kv0 = 0; kv0 < SS; kv0 += 64){
        __syncthreads();   // prev PV reads of sK/sV done
        {
            const float* kp = Kg + (size_t)(kv0 + cprow)*HD + cpcol;
            const float* vp = Vg + (size_t)(kv0 + cprow)*HD + cpcol;
            float* ksm = sK + cprow*72 + cpcol;
            float* vsm = sV + cprow*72 + cpcol;
            #pragma unroll
            for (int i = 0; i < 4; i++){
                float4 u = *(const float4*)(kp + 4*i);
                *(float4*)(ksm + 4*i) = make_float4(to_tf32(u.x), to_tf32(u.y),
                                                    to_tf32(u.z), to_tf32(u.w));
                float4 w = *(const float4*)(vp + 4*i);
                *(float4*)(vsm + 4*i) = make_float4(to_tf32(w.x), to_tf32(w.y),
                                                    to_tf32(w.z), to_tf32(w.w));
            }
        }
        __syncthreads();

        // S = Q @ K^T  (16 rows x 64 cols per warp)
        float s[8][4] = {};
        #pragma unroll
        for (int ks = 0; ks < 8; ks++){
            #pragma unroll
            for (int nt = 0; nt < 8; nt++){
                const float* kb = sK + (nt*8 + lr)*72 + ks*8 + lc;
                mma_tf32(s[nt], qa[ks][0], qa[ks][1], qa[ks][2], qa[ks][3],
                         kb[0], kb[4]);
            }
        }

        // online softmax
        float mx0 = -1e30f, mx1 = -1e30f;
        #pragma unroll
        for (int nt = 0; nt < 8; nt++){
            mx0 = fmaxf(mx0, fmaxf(s[nt][0], s[nt][1]));
            mx1 = fmaxf(mx1, fmaxf(s[nt][2], s[nt][3]));
        }
        mx0 = fmaxf(mx0, __shfl_xor_sync(0xffffffffu, mx0, 1));
        mx0 = fmaxf(mx0, __shfl_xor_sync(0xffffffffu, mx0, 2));
        mx1 = fmaxf(mx1, __shfl_xor_sync(0xffffffffu, mx1, 1));
        mx1 = fmaxf(mx1, __shfl_xor_sync(0xffffffffu, mx1, 2));
        float mn0 = fmaxf(m0, mx0), mn1 = fmaxf(m1, mx1);
        float al0 = __expf(m0 - mn0), al1 = __expf(m1 - mn1);
        m0 = mn0; m1 = mn1;
        float sm0 = 0.f, sm1 = 0.f;
        #pragma unroll
        for (int nt = 0; nt < 8; nt++){
            float p0 = __expf(s[nt][0] - mn0);
            float p1 = __expf(s[nt][1] - mn0);
            float p2 = __expf(s[nt][2] - mn1);
            float p3 = __expf(s[nt][3] - mn1);
            sm0 += p0 + p1; sm1 += p2 + p3;
            float* pw = sP + (wm + lr)*72 + nt*8 + 2*lc;
            *(float2*)pw          = make_float2(to_tf32(p0), to_tf32(p1));
            *(float2*)(pw + 8*72) = make_float2(to_tf32(p2), to_tf32(p3));
        }
        sm0 += __shfl_xor_sync(0xffffffffu, sm0, 1);
        sm0 += __shfl_xor_sync(0xffffffffu, sm0, 2);
        sm1 += __shfl_xor_sync(0xffffffffu, sm1, 1);
        sm1 += __shfl_xor_sync(0xffffffffu, sm1, 2);
        l0 = l0*al0 + sm0;
        l1 = l1*al1 + sm1;
        #pragma unroll
        for (int nt = 0; nt < 8; nt++){
            o[nt][0] *= al0; o[nt][1] *= al0;
            o[nt][2] *= al1; o[nt][3] *= al1;
        }
        __syncwarp();   // P rows are exchanged only within this warp

        // O += P @ V   (V in natural [kv][hd] layout IS the col-major B operand)
        #pragma unroll
        for (int ks = 0; ks < 8; ks++){
            const float* pa = sP + (wm + lr)*72 + ks*8 + lc;
            float a0 = pa[0], a1 = pa[8*72], a2 = pa[4], a3 = pa[8*72 + 4];
            #pragma unroll
            for (int nt = 0; nt < 8; nt++){
                const float* vb = sV + (ks*8 + lc)*72 + nt*8 + lr;
                mma_tf32(o[nt], a0, a1, a2, a3, vb[0], vb[4*72]);
            }
        }
    }

    float inv0 = 1.f/l0, inv1 = 1.f/l1;
    float* O0 = g_ao + ((size_t)(b*SS + q0 + wm + lr))*DD + h*HD;
    float* O1 = O0 + 8*DD;
    #pragma unroll
    for (int nt = 0; nt < 8; nt++){
        *(float2*)(O0 + nt*8 + 2*lc) = make_float2(o[nt][0]*inv0, o[nt][1]*inv0);
        *(float2*)(O1 + nt*8 + 2*lc) = make_float2(o[nt][2]*inv1, o[nt][3]*inv1);
    }
}

// ---------------------------------------------------------------------------
// Output projection + bias.  grid (8, 128)
// ---------------------------------------------------------------------------
__global__ void __launch_bounds__(256) oproj_kernel(
    const float* __restrict__ Wo, const float* __restrict__ bo,
    float* __restrict__ out)
{
    extern __shared__ float sm[];
    float d[2][8][4] = {};
    gemm_main(g_ao + (size_t)blockIdx.y*128*DD, Wo + (size_t)blockIdx.x*128*DD, sm, d);

    const int tid = threadIdx.x;
    const int warp = tid >> 5, lane = tid & 31;
    const int wm = (warp >> 1) * 32, wn = (warp & 1) * 64;
    const int lr = lane >> 2, lc = lane & 3;

    #pragma unroll
    for (int mt = 0; mt < 2; mt++){
        #pragma unroll
        for (int rh = 0; rh < 2; rh++){
            int m = blockIdx.y*128 + wm + mt*16 + rh*8 + lr;
            #pragma unroll
            for (int nt = 0; nt < 8; nt++){
                int n = blockIdx.x*128 + wn + nt*8 + 2*lc;
                float2 bi = *(const float2*)(bo + n);
                *(float2*)(out + (size_t)m*DD + n) =
                    make_float2(d[mt][nt][rh*2+0] + bi.x,
                                d[mt][nt][rh*2+1] + bi.y);
            }
        }
    }
}

extern "C" void kernel_launch(void* const* d_in, const int* in_sizes, int n_in,
                              void* d_out, int out_size)
{
    const float* x    = (const float*)d_in[0];
    const float* cosp = (const float*)d_in[1];
    const float* sinp = (const float*)d_in[2];
    const float* Wq   = (const float*)d_in[3];
    const float* bq   = (const float*)d_in[4];
    const float* Wk   = (const float*)d_in[5];
    const float* bk   = (const float*)d_in[6];
    const float* Wv   = (const float*)d_in[7];
    const float* bv   = (const float*)d_in[8];
    const float* Wo   = (const float*)d_in[9];
    const float* bo   = (const float*)d_in[10];
    float* out = (float*)d_out;
    (void)in_sizes; (void)n_in; (void)out_size;

    const int gemm_smem = 12288 * 4;   // 49152 B
    const int attn_smem = 72 * 256 * 4; // 73728 B
    cudaFuncSetAttribute((const void*)qkv_kernel,
                         cudaFuncAttributeMaxDynamicSharedMemorySize, gemm_smem);
    cudaFuncSetAttribute((const void*)attn_kernel,
                         cudaFuncAttributeMaxDynamicSharedMemorySize, attn_smem);
    cudaFuncSetAttribute((const void*)oproj_kernel,
                         cudaFuncAttributeMaxDynamicSharedMemorySize, gemm_smem);

    qkv_kernel<<<dim3(8, 128, 3), 256, gemm_smem>>>(x, Wq, bq, Wk, bk, Wv, bv, cosp, sinp);
    attn_kernel<<<dim3(SS/128, NH, BB), 256, attn_smem>>>();
    oproj_kernel<<<dim3(8, 128), 256, gemm_smem>>>(Wo, bo, out);
}

// round 3
// speedup vs baseline: 4.2918x; 1.4533x over previous
#include <cuda_runtime.h>
#include <cstdint>

#define BB 16
#define SS 1024
#define DD 1024
#define NH 16
#define HD 64

// Scratch (allocation-free requirement)
__device__ float g_q[(size_t)BB*NH*SS*HD];
__device__ float g_k[(size_t)BB*NH*SS*HD];
__device__ float g_v[(size_t)BB*NH*SS*HD];
__device__ float g_ao[(size_t)BB*SS*DD];
__device__ float g_xr[(size_t)BB*SS*DD];     // tf32-rounded x
__device__ float g_wr[(size_t)4*DD*DD];      // tf32-rounded Wq,Wk,Wv,Wo

__device__ __forceinline__ float to_tf32(float x){
    float r; asm("cvt.rna.tf32.f32 %0, %1;" : "=f"(r) : "f"(x)); return r;
}

__device__ __forceinline__ void mma_tf32(float* d,
    float a0, float a1, float a2, float a3, float b0, float b1)
{
    asm volatile("mma.sync.aligned.m16n8k8.row.col.f32.tf32.tf32.f32 "
        "{%0,%1,%2,%3}, {%4,%5,%6,%7}, {%8,%9}, {%0,%1,%2,%3};"
        : "+f"(d[0]), "+f"(d[1]), "+f"(d[2]), "+f"(d[3])
        : "r"(__float_as_uint(a0)), "r"(__float_as_uint(a1)),
          "r"(__float_as_uint(a2)), "r"(__float_as_uint(a3)),
          "r"(__float_as_uint(b0)), "r"(__float_as_uint(b1)));
}

// ---------------------------------------------------------------------------
// Prepass: tf32-round x and all 4 weight matrices (one-time, memory-bound).
// ---------------------------------------------------------------------------
__global__ void __launch_bounds__(256) round_kernel(
    const float* __restrict__ x,
    const float* __restrict__ Wq, const float* __restrict__ Wk,
    const float* __restrict__ Wv, const float* __restrict__ Wo)
{
    const size_t X4 = (size_t)BB*SS*DD/4;       // 4M float4
    const size_t W4 = (size_t)DD*DD/4;          // 256K float4 each
    size_t idx = (size_t)blockIdx.x * 256 + threadIdx.x;
    const float4* src; float4* dst;
    if (idx < X4){
        src = (const float4*)x; dst = (float4*)g_xr;
    } else {
        size_t w = idx - X4;
        int which = (int)(w / W4);
        idx = w - (size_t)which*W4;
        src = (const float4*)((which==0)?Wq:(which==1)?Wk:(which==2)?Wv:Wo);
        dst = (float4*)g_wr + (size_t)which*W4;
    }
    float4 v = src[idx];
    dst[idx] = make_float4(to_tf32(v.x), to_tf32(v.y), to_tf32(v.z), to_tf32(v.w));
}

// Store 8 consecutive-k values into k-pair-permuted smem layout (pre-rounded).
__device__ __forceinline__ void st_pair(float* s, float4 u, float4 v){
    ((float2*)s)[0] = make_float2(u.x, v.x);
    ((float2*)s)[1] = make_float2(u.y, v.y);
    ((float2*)s)[2] = make_float2(u.z, v.z);
    ((float2*)s)[3] = make_float2(u.w, v.w);
}

// One k-tile (16) of mma work from permuted smem tiles (stride 24 floats).
__device__ __forceinline__ void gemm_step(const float* sA, const float* sB,
                                          int wm, int wn, int lr, int lc,
                                          float (&d)[2][8][4])
{
    #pragma unroll
    for (int ks = 0; ks < 2; ks++){
        const float* sa = sA + (wm + lr)*24 + ks*8 + 2*lc;
        float2 a02_0 = *(const float2*)(sa);
        float2 a13_0 = *(const float2*)(sa + 8*24);
        float2 a02_1 = *(const float2*)(sa + 16*24);
        float2 a13_1 = *(const float2*)(sa + 24*24);
        #pragma unroll
        for (int nt = 0; nt < 8; nt++){
            float2 b = *(const float2*)(sB + (wn + nt*8 + lr)*24 + ks*8 + 2*lc);
            mma_tf32(d[0][nt], a02_0.x, a13_0.x, a02_0.y, a13_0.y, b.x, b.y);
            mma_tf32(d[1][nt], a02_1.x, a13_1.x, a02_1.y, a13_1.y, b.x, b.y);
        }
    }
}

// Shared GEMM mainloop: C(128x128) = A(128xK) @ B(128xK)^T, K=1024.
__device__ __forceinline__ void gemm_main(const float* __restrict__ Ab,
                                          const float* __restrict__ Bb,
                                          float* sm, float (&d)[2][8][4])
{
    float* bufA[2] = {sm,        sm + 3072};
    float* bufB[2] = {sm + 6144, sm + 9216};

    const int tid  = threadIdx.x;
    const int warp = tid >> 5, lane = tid & 31;
    const int wm = (warp >> 1) * 32, wn = (warp & 1) * 64;
    const int lr = lane >> 2, lc = lane & 3;

    const int ldrow = tid >> 1;
    const int kg    = (tid & 1) * 8;
    const float* aptr = Ab + (size_t)ldrow * DD + kg;
    const float* bptr = Bb + (size_t)ldrow * DD + kg;
    const int soff = ldrow*24 + kg;

    float4 ua = *(const float4*)(aptr);
    float4 va = *(const float4*)(aptr + 4);
    float4 ub = *(const float4*)(bptr);
    float4 vb = *(const float4*)(bptr + 4);
    st_pair(bufA[0] + soff, ua, va);
    st_pair(bufB[0] + soff, ub, vb);
    __syncthreads();

    #pragma unroll 2
    for (int kt = 0; kt < 64; kt++){
        int cur = kt & 1;
        if (kt < 63){
            const float* ap = aptr + (kt+1)*16;
            const float* bp = bptr + (kt+1)*16;
            ua = *(const float4*)(ap);
            va = *(const float4*)(ap + 4);
            ub = *(const float4*)(bp);
            vb = *(const float4*)(bp + 4);
        }
        gemm_step(bufA[cur], bufB[cur], wm, wn, lr, lc, d);
        if (kt < 63){
            st_pair(bufA[cur^1] + soff, ua, va);
            st_pair(bufB[cur^1] + soff, ub, vb);
            __syncthreads();
        }
    }
}

// ---------------------------------------------------------------------------
// Fused QKV projection + bias + RoPE.  grid (8, 128, 3).
// Outputs are tf32-pre-rounded; Q additionally pre-scaled by HD^-0.5.
// ---------------------------------------------------------------------------
__global__ void __launch_bounds__(256, 2) qkv_kernel(
    const float* __restrict__ bq, const float* __restrict__ bk,
    const float* __restrict__ bv,
    const float* __restrict__ cosp, const float* __restrict__ sinp)
{
    extern __shared__ float sm[];
    const int z = blockIdx.z;
    const float* bias = (z == 0) ? bq : (z == 1) ? bk : bv;
    float* outp       = (z == 0) ? g_q : (z == 1) ? g_k : g_v;

    float d[2][8][4] = {};
    gemm_main(g_xr + (size_t)blockIdx.y*128*DD,
              g_wr + (size_t)z*DD*DD + (size_t)blockIdx.x*128*DD, sm, d);

    const int tid = threadIdx.x;
    const int warp = tid >> 5, lane = tid & 31;
    const int wm = (warp >> 1) * 32, wn = (warp & 1) * 64;
    const int lr = lane >> 2, lc = lane & 3;
    const float qs = (z == 0) ? 0.125f : 1.0f;

    #pragma unroll
    for (int mt = 0; mt < 2; mt++){
        #pragma unroll
        for (int rh = 0; rh < 2; rh++){
            int m = blockIdx.y*128 + wm + mt*16 + rh*8 + lr;
            int bb = m >> 10, s = m & 1023;
            #pragma unroll
            for (int nt = 0; nt < 8; nt++){
                int n = blockIdx.x*128 + wn + nt*8 + 2*lc;
                float2 bi = *(const float2*)(bias + n);
                float v0 = d[mt][nt][rh*2+0] + bi.x;
                float v1 = d[mt][nt][rh*2+1] + bi.y;
                int hh = n >> 6, hd0 = n & 63;
                if (z < 2){
                    float2 cs = *(const float2*)(cosp + s*HD + hd0);
                    float2 sn = *(const float2*)(sinp + s*HD + hd0);
                    float r0 = v0*cs.x - v1*sn.x;
                    float r1 = v1*cs.y + v0*sn.y;
                    v0 = r0; v1 = r1;
                }
                *(float2*)(outp + ((size_t)(bb*NH + hh)*SS + s)*HD + hd0) =
                    make_float2(to_tf32(v0*qs), to_tf32(v1*qs));
            }
        }
    }
}

// ---------------------------------------------------------------------------
// Flash attention, tf32 mma.  grid (8, NH, BB), 256 thr, dyn smem 72KB.
// Inputs pre-rounded (Q pre-scaled); output pre-rounded for oproj.
// ---------------------------------------------------------------------------
__global__ void __launch_bounds__(256) attn_kernel()
{
    extern __shared__ float sm[];
    float* sK = sm;            // [64][72]
    float* sV = sm + 64*72;    // [64][72]
    float* sP = sm + 2*64*72;  // [128][72]

    const int tid = threadIdx.x;
    const int warp = tid >> 5, lane = tid & 31;
    const int lr = lane >> 2, lc = lane & 3;
    const int wm = warp * 16;
    const int q0 = blockIdx.x * 128;
    const int h = blockIdx.y, b = blockIdx.z;
    const int bh = b*NH + h;
    const float* Qg = g_q + (size_t)bh*SS*HD;
    const float* Kg = g_k + (size_t)bh*SS*HD;
    const float* Vg = g_v + (size_t)bh*SS*HD;

    // Q fragments resident in registers (already scaled + tf32-rounded)
    float qa[8][4];
    {
        const float* q0p = Qg + (size_t)(q0 + wm + lr)*HD;
        const float* q1p = q0p + 8*HD;
        #pragma unroll
        for (int ks = 0; ks < 8; ks++){
            int c = ks*8 + lc;
            qa[ks][0] = q0p[c];
            qa[ks][1] = q1p[c];
            qa[ks][2] = q0p[c+4];
            qa[ks][3] = q1p[c+4];
        }
    }

    float o[8][4] = {};
    float m0 = -1e30f, m1 = -1e30f, l0 = 0.f, l1 = 0.f;

    const int cprow = tid >> 2;          // 0..63
    const int cpcol = (tid & 3) * 16;

    for (int kv0 = 0; kv0 < SS; kv0 += 64){
        __syncthreads();   // prev PV reads of sK/sV done
        {
            const float* kp = Kg + (size_t)(kv0 + cprow)*HD + cpcol;
            const float* vp = Vg + (size_t)(kv0 + cprow)*HD + cpcol;
            float* ksm = sK + cprow*72 + cpcol;
            float* vsm = sV + cprow*72 + cpcol;
            #pragma unroll
            for (int i = 0; i < 4; i++){
                *(float4*)(ksm + 4*i) = *(const float4*)(kp + 4*i);
                *(float4*)(vsm + 4*i) = *(const float4*)(vp + 4*i);
            }
        }
        __syncthreads();

        // S = Q @ K^T  (16 rows x 64 cols per warp)
        float s[8][4] = {};
        #pragma unroll
        for (int ks = 0; ks < 8; ks++){
            #pragma unroll
            for (int nt = 0; nt < 8; nt++){
                const float* kb = sK + (nt*8 + lr)*72 + ks*8 + lc;
                mma_tf32(s[nt], qa[ks][0], qa[ks][1], qa[ks][2], qa[ks][3],
                         kb[0], kb[4]);
            }
        }

        // online softmax
        float mx0 = -1e30f, mx1 = -1e30f;
        #pragma unroll
        for (int nt = 0; nt < 8; nt++){
            mx0 = fmaxf(mx0, fmaxf(s[nt][0], s[nt][1]));
            mx1 = fmaxf(mx1, fmaxf(s[nt][2], s[nt][3]));
        }
        mx0 = fmaxf(mx0, __shfl_xor_sync(0xffffffffu, mx0, 1));
        mx0 = fmaxf(mx0, __shfl_xor_sync(0xffffffffu, mx0, 2));
        mx1 = fmaxf(mx1, __shfl_xor_sync(0xffffffffu, mx1, 1));
        mx1 = fmaxf(mx1, __shfl_xor_sync(0xffffffffu, mx1, 2));
        float mn0 = fmaxf(m0, mx0), mn1 = fmaxf(m1, mx1);
        float al0 = __expf(m0 - mn0), al1 = __expf(m1 - mn1);
        m0 = mn0; m1 = mn1;
        float sm0 = 0.f, sm1 = 0.f;
        #pragma unroll
        for (int nt = 0; nt < 8; nt++){
            float p0 = __expf(s[nt][0] - mn0);
            float p1 = __expf(s[nt][1] - mn0);
            float p2 = __expf(s[nt][2] - mn1);
            float p3 = __expf(s[nt][3] - mn1);
            sm0 += p0 + p1; sm1 += p2 + p3;
            float* pw = sP + (wm + lr)*72 + nt*8 + 2*lc;
            *(float2*)pw          = make_float2(to_tf32(p0), to_tf32(p1));
            *(float2*)(pw + 8*72) = make_float2(to_tf32(p2), to_tf32(p3));
        }
        sm0 += __shfl_xor_sync(0xffffffffu, sm0, 1);
        sm0 += __shfl_xor_sync(0xffffffffu, sm0, 2);
        sm1 += __shfl_xor_sync(0xffffffffu, sm1, 1);
        sm1 += __shfl_xor_sync(0xffffffffu, sm1, 2);
        l0 = l0*al0 + sm0;
        l1 = l1*al1 + sm1;
        #pragma unroll
        for (int nt = 0; nt < 8; nt++){
            o[nt][0] *= al0; o[nt][1] *= al0;
            o[nt][2] *= al1; o[nt][3] *= al1;
        }
        __syncwarp();   // P rows exchanged only within this warp

        // O += P @ V
        #pragma unroll
        for (int ks = 0; ks < 8; ks++){
            const float* pa = sP + (wm + lr)*72 + ks*8 + lc;
            float a0 = pa[0], a1 = pa[8*72], a2 = pa[4], a3 = pa[8*72 + 4];
            #pragma unroll
            for (int nt = 0; nt < 8; nt++){
                const float* vb = sV + (ks*8 + lc)*72 + nt*8 + lr;
                mma_tf32(o[nt], a0, a1, a2, a3, vb[0], vb[4*72]);
            }
        }
    }

    float inv0 = 1.f/l0, inv1 = 1.f/l1;
    float* O0 = g_ao + ((size_t)(b*SS + q0 + wm + lr))*DD + h*HD;
    float* O1 = O0 + 8*DD;
    #pragma unroll
    for (int nt = 0; nt < 8; nt++){
        *(float2*)(O0 + nt*8 + 2*lc) = make_float2(to_tf32(o[nt][0]*inv0),
                                                   to_tf32(o[nt][1]*inv0));
        *(float2*)(O1 + nt*8 + 2*lc) = make_float2(to_tf32(o[nt][2]*inv1),
                                                   to_tf32(o[nt][3]*inv1));
    }
}

// ---------------------------------------------------------------------------
// Output projection + bias.  grid (8, 128)
// ---------------------------------------------------------------------------
__global__ void __launch_bounds__(256, 2) oproj_kernel(
    const float* __restrict__ bo, float* __restrict__ out)
{
    extern __shared__ float sm[];
    float d[2][8][4] = {};
    gemm_main(g_ao + (size_t)blockIdx.y*128*DD,
              g_wr + (size_t)3*DD*DD + (size_t)blockIdx.x*128*DD, sm, d);

    const int tid = threadIdx.x;
    const int warp = tid >> 5, lane = tid & 31;
    const int wm = (warp >> 1) * 32, wn = (warp & 1) * 64;
    const int lr = lane >> 2, lc = lane & 3;

    #pragma unroll
    for (int mt = 0; mt < 2; mt++){
        #pragma unroll
        for (int rh = 0; rh < 2; rh++){
            int m = blockIdx.y*128 + wm + mt*16 + rh*8 + lr;
            #pragma unroll
            for (int nt = 0; nt < 8; nt++){
                int n = blockIdx.x*128 + wn + nt*8 + 2*lc;
                float2 bi = *(const float2*)(bo + n);
                *(float2*)(out + (size_t)m*DD + n) =
                    make_float2(d[mt][nt][rh*2+0] + bi.x,
                                d[mt][nt][rh*2+1] + bi.y);
            }
        }
    }
}

extern "C" void kernel_launch(void* const* d_in, const int* in_sizes, int n_in,
                              void* d_out, int out_size)
{
    const float* x    = (const float*)d_in[0];
    const float* cosp = (const float*)d_in[1];
    const float* sinp = (const float*)d_in[2];
    const float* Wq   = (const float*)d_in[3];
    const float* bq   = (const float*)d_in[4];
    const float* Wk   = (const float*)d_in[5];
    const float* bk   = (const float*)d_in[6];
    const float* Wv   = (const float*)d_in[7];
    const float* bv   = (const float*)d_in[8];
    const float* Wo   = (const float*)d_in[9];
    const float* bo   = (const float*)d_in[10];
    float* out = (float*)d_out;
    (void)in_sizes; (void)n_in; (void)out_size;

    const int gemm_smem = 12288 * 4;    // 49152 B
    const int attn_smem = 72 * 256 * 4; // 73728 B
    cudaFuncSetAttribute((const void*)qkv_kernel,
                         cudaFuncAttributeMaxDynamicSharedMemorySize, gemm_smem);
    cudaFuncSetAttribute((const void*)attn_kernel,
                         cudaFuncAttributeMaxDynamicSharedMemorySize, attn_smem);
    cudaFuncSetAttribute((const void*)oproj_kernel,
                         cudaFuncAttributeMaxDynamicSharedMemorySize, gemm_smem);

    const size_t total4 = (size_t)BB*SS*DD/4 + (size_t)4*DD*DD/4;  // 5M float4
    round_kernel<<<(unsigned)((total4 + 255)/256), 256>>>(x, Wq, Wk, Wv, Wo);
    qkv_kernel<<<dim3(8, 128, 3), 256, gemm_smem>>>(bq, bk, bv, cosp, sinp);
    attn_kernel<<<dim3(SS/128, NH, BB), 256, attn_smem>>>();
    oproj_kernel<<<dim3(8, 128), 256, gemm_smem>>>(bo, out);
}